// round 1
// baseline (speedup 1.0000x reference)
#include <cuda_runtime.h>
#include <math.h>

// Problem constants
constexpr int Bc  = 8;
constexpr int Sc  = 2048;
constexpr int Dc  = 1024;
constexpr int NHc = 16;
constexpr int HDc = 64;
constexpr int Mc  = Bc * Sc;            // 16384 rows
constexpr float GATE_CAP_F = 15.0f;
constexpr float EPS_F = 1e-5f;
constexpr size_t OUT_Y = (size_t)Mc * Dc;   // 16,777,216 floats, then H_final

// ---------------- scratch (static device arrays; no cudaMalloc allowed) ----
__device__ float g_xn[(size_t)Mc * Dc];
__device__ float g_q [(size_t)Mc * Dc];
__device__ float g_k [(size_t)Mc * Dc];
__device__ float g_v [(size_t)Mc * Dc];
__device__ float g_h [(size_t)Mc * Dc];
__device__ float g_ig[(size_t)Mc * NHc];
__device__ float g_fg[(size_t)Mc * NHc];
__device__ float g_og[(size_t)Mc * NHc];

// ---------------- RMSNorm: one block per row, 256 threads, float4 ----------
__global__ __launch_bounds__(256) void rmsnorm_kernel(const float* __restrict__ x,
                                                      const float* __restrict__ w)
{
    int row = blockIdx.x;
    const float4* xr = (const float4*)(x + (size_t)row * Dc);
    float4 v = xr[threadIdx.x];                      // 256 * 4 = 1024 elems
    float ss = v.x * v.x + v.y * v.y + v.z * v.z + v.w * v.w;
    #pragma unroll
    for (int o = 16; o; o >>= 1) ss += __shfl_xor_sync(~0u, ss, o);

    __shared__ float sred[8];
    __shared__ float s_scale;
    if ((threadIdx.x & 31) == 0) sred[threadIdx.x >> 5] = ss;
    __syncthreads();
    if (threadIdx.x == 0) {
        float tot = 0.f;
        #pragma unroll
        for (int i = 0; i < 8; i++) tot += sred[i];
        float var = tot * (1.0f / (float)Dc);
        s_scale = 1.0f / sqrtf(var + EPS_F);
    }
    __syncthreads();
    float sc = s_scale;
    const float4* wr = (const float4*)w;
    float4 ww = wr[threadIdx.x];
    float4 o4;
    o4.x = v.x * sc * ww.x;
    o4.y = v.y * sc * ww.y;
    o4.z = v.z * sc * ww.z;
    o4.w = v.w * sc * ww.w;
    ((float4*)(g_xn + (size_t)row * Dc))[threadIdx.x] = o4;
}

// ---------------- SGEMM: C[M,N] = A[M,K] * Bw[N,K]^T (+ residual) ----------
// Classic 128x128x8 fp32 tile, 256 threads, 8x8 per thread.
template<bool ADD_RES>
__global__ __launch_bounds__(256) void sgemm_kernel(const float* __restrict__ A,
                                                    const float* __restrict__ Bw,
                                                    const float* __restrict__ res,
                                                    float* __restrict__ C,
                                                    int M, int N, int K)
{
    constexpr int BM = 128, BN = 128, BK = 8, TM = 8, TN = 8;
    __shared__ float As[BK][BM];
    __shared__ float Bs[BK][BN];
    const int tid  = threadIdx.x;
    const int brow = blockIdx.y * BM;
    const int bcol = blockIdx.x * BN;
    const int lRow = tid >> 1;          // 0..127
    const int lCol = (tid & 1) * 4;     // 0 or 4
    const int ty   = tid >> 4;          // 0..15
    const int tx   = tid & 15;          // 0..15

    float acc[TM][TN];
    #pragma unroll
    for (int i = 0; i < TM; i++)
        #pragma unroll
        for (int j = 0; j < TN; j++) acc[i][j] = 0.f;

    const float* Ab = A  + (size_t)(brow + lRow) * K + lCol;
    const float* Bp = Bw + (size_t)(bcol + lRow) * K + lCol;

    for (int k0 = 0; k0 < K; k0 += BK) {
        float4 a4 = *(const float4*)(Ab + k0);
        float4 b4 = *(const float4*)(Bp + k0);
        As[lCol + 0][lRow] = a4.x; As[lCol + 1][lRow] = a4.y;
        As[lCol + 2][lRow] = a4.z; As[lCol + 3][lRow] = a4.w;
        Bs[lCol + 0][lRow] = b4.x; Bs[lCol + 1][lRow] = b4.y;
        Bs[lCol + 2][lRow] = b4.z; Bs[lCol + 3][lRow] = b4.w;
        __syncthreads();
        #pragma unroll
        for (int kk = 0; kk < BK; kk++) {
            float ra[TM], rb[TN];
            #pragma unroll
            for (int i = 0; i < TM; i++) ra[i] = As[kk][ty * TM + i];
            #pragma unroll
            for (int j = 0; j < TN; j++) rb[j] = Bs[kk][tx * TN + j];
            #pragma unroll
            for (int i = 0; i < TM; i++)
                #pragma unroll
                for (int j = 0; j < TN; j++)
                    acc[i][j] = fmaf(ra[i], rb[j], acc[i][j]);
        }
        __syncthreads();
    }

    #pragma unroll
    for (int i = 0; i < TM; i++) {
        size_t r = (size_t)(brow + ty * TM + i) * N + bcol + tx * TN;
        #pragma unroll
        for (int j = 0; j < TN; j += 4) {
            float4 o4;
            o4.x = acc[i][j + 0]; o4.y = acc[i][j + 1];
            o4.z = acc[i][j + 2]; o4.w = acc[i][j + 3];
            if (ADD_RES) {
                float4 rv = *(const float4*)(res + r + j);
                o4.x += rv.x; o4.y += rv.y; o4.z += rv.z; o4.w += rv.w;
            }
            *(float4*)(C + r + j) = o4;
        }
    }
}

// ---------------- gates: z = xn @ W{i,f,o}^T -> sigmoid(softcap(z)) --------
// One block handles 8 rows; warp w owns row w; 48 warp-reduced dots each.
__global__ __launch_bounds__(256) void gates_kernel(const float* __restrict__ Wi,
                                                    const float* __restrict__ Wf,
                                                    const float* __restrict__ Wo)
{
    __shared__ float sx[8][Dc];
    int row0 = blockIdx.x * 8;
    for (int idx = threadIdx.x; idx < 8 * Dc; idx += 256)
        sx[idx >> 10][idx & 1023] = g_xn[(size_t)(row0 + (idx >> 10)) * Dc + (idx & 1023)];
    __syncthreads();

    int w    = threadIdx.x >> 5;
    int lane = threadIdx.x & 31;
    int row  = row0 + w;
    const float* xr = sx[w];

    for (int c = 0; c < 48; c++) {
        const float* wp = (c < 16) ? (Wi + (size_t)c * Dc)
                        : (c < 32) ? (Wf + (size_t)(c - 16) * Dc)
                                   : (Wo + (size_t)(c - 32) * Dc);
        float s = 0.f;
        #pragma unroll 8
        for (int k = lane; k < Dc; k += 32)
            s = fmaf(xr[k], __ldg(wp + k), s);
        #pragma unroll
        for (int o = 16; o; o >>= 1) s += __shfl_xor_sync(~0u, s, o);
        if (lane == 0) {
            float z  = GATE_CAP_F * tanhf(s * (1.0f / GATE_CAP_F));
            float gv = 1.0f / (1.0f + expf(-z));
            float* dst = (c < 16) ? g_ig : (c < 32) ? g_fg : g_og;
            dst[(size_t)row * NHc + (c & 15)] = gv;
        }
    }
}

// ---------------- recurrence: one block per (b,h) chain --------------------
// 256 threads: thread owns H[d, e] for e = tid>>2, d in [ (tid&3)*16, +16 ).
// Per step: Hnew = f*H + (i*v_e)*k_d ; acc += q_d*Hnew ; reduce over 4 lanes.
__global__ __launch_bounds__(256) void recurrence_kernel(float* __restrict__ Hfinal_out)
{
    constexpr int CH = 16;                     // time-chunk staged in smem
    int bh = blockIdx.x;                       // 0..127
    int b  = bh >> 4, h = bh & 15;
    int tid   = threadIdx.x;
    int e     = tid >> 2;                      // 0..63
    int dg    = tid & 3;                       // 0..3
    int dbase = dg * 16;

    __shared__ float sq[CH][64], sk[CH][64], sv[CH][64], sh[CH][64];
    __shared__ float sgi[CH], sgf[CH], sgo[CH];

    float4 H4[4] = {};                         // H[dbase..dbase+15][e]

    size_t baseq = (size_t)b * Sc * Dc + (size_t)h * HDc;
    size_t baseg = (size_t)b * Sc * NHc + h;

    for (int t0 = 0; t0 < Sc; t0 += CH) {
        for (int idx = tid; idx < CH * 64; idx += 256) {
            int t = idx >> 6, d = idx & 63;
            size_t g = baseq + (size_t)(t0 + t) * Dc + d;
            sq[t][d] = g_q[g];
            sk[t][d] = g_k[g];
            sv[t][d] = g_v[g];
        }
        if (tid < CH) {
            size_t gg = baseg + (size_t)(t0 + tid) * NHc;
            sgi[tid] = g_ig[gg];
            sgf[tid] = g_fg[gg];
            sgo[tid] = g_og[gg];
        }
        __syncthreads();

        #pragma unroll 4
        for (int t = 0; t < CH; t++) {
            float f  = sgf[t];
            float iv = sgi[t] * sv[t][e];
            const float4* q4 = (const float4*)(&sq[t][dbase]);
            const float4* k4 = (const float4*)(&sk[t][dbase]);
            float acc = 0.f;
            #pragma unroll
            for (int j = 0; j < 4; j++) {
                float4 kk = k4[j];
                float4 qq = q4[j];
                H4[j].x = fmaf(f, H4[j].x, kk.x * iv); acc = fmaf(qq.x, H4[j].x, acc);
                H4[j].y = fmaf(f, H4[j].y, kk.y * iv); acc = fmaf(qq.y, H4[j].y, acc);
                H4[j].z = fmaf(f, H4[j].z, kk.z * iv); acc = fmaf(qq.z, H4[j].z, acc);
                H4[j].w = fmaf(f, H4[j].w, kk.w * iv); acc = fmaf(qq.w, H4[j].w, acc);
            }
            acc += __shfl_xor_sync(~0u, acc, 1);   // reduce across dg (lane bits 0,1)
            acc += __shfl_xor_sync(~0u, acc, 2);
            if (dg == 0) sh[t][e] = acc * sgo[t];
        }
        __syncthreads();

        for (int idx = tid; idx < CH * 64; idx += 256) {
            int t = idx >> 6, d = idx & 63;
            g_h[baseq + (size_t)(t0 + t) * Dc + d] = sh[t][d];
        }
        // next-iter load writes sq/sk/sv (safe: compute done); the sync after
        // that load also fences sh reads above against next compute's writes.
    }

    // H_final layout: [b][h][d][e]
    float* Hf = Hfinal_out + (size_t)bh * 64 * 64;
    #pragma unroll
    for (int j = 0; j < 4; j++) {
        int d = dbase + j * 4;
        Hf[(size_t)(d + 0) * 64 + e] = H4[j].x;
        Hf[(size_t)(d + 1) * 64 + e] = H4[j].y;
        Hf[(size_t)(d + 2) * 64 + e] = H4[j].z;
        Hf[(size_t)(d + 3) * 64 + e] = H4[j].w;
    }
}

// ---------------- launch ---------------------------------------------------
extern "C" void kernel_launch(void* const* d_in, const int* in_sizes, int n_in,
                              void* d_out, int out_size)
{
    const float* x    = (const float*)d_in[0];
    const float* Wq   = (const float*)d_in[1];
    const float* Wk   = (const float*)d_in[2];
    const float* Wv   = (const float*)d_in[3];
    const float* Wi   = (const float*)d_in[4];
    const float* Wf   = (const float*)d_in[5];
    const float* Wo   = (const float*)d_in[6];
    const float* Wout = (const float*)d_in[7];
    const float* lnw  = (const float*)d_in[8];
    float* out = (float*)d_out;

    float *p_xn, *p_q, *p_k, *p_v, *p_h;
    cudaGetSymbolAddress((void**)&p_xn, g_xn);
    cudaGetSymbolAddress((void**)&p_q,  g_q);
    cudaGetSymbolAddress((void**)&p_k,  g_k);
    cudaGetSymbolAddress((void**)&p_v,  g_v);
    cudaGetSymbolAddress((void**)&p_h,  g_h);

    // 1) RMSNorm
    rmsnorm_kernel<<<Mc, 256>>>(x, lnw);

    // 2) Q/K/V projections: 16384 x 1024 x 1024 each
    dim3 ggrid(Dc / 128, Mc / 128);
    sgemm_kernel<false><<<ggrid, 256>>>(p_xn, Wq, nullptr, p_q, Mc, Dc, Dc);
    sgemm_kernel<false><<<ggrid, 256>>>(p_xn, Wk, nullptr, p_k, Mc, Dc, Dc);
    sgemm_kernel<false><<<ggrid, 256>>>(p_xn, Wv, nullptr, p_v, Mc, Dc, Dc);

    // 3) gates (i, f, o): 16384 x 48 x 1024 + softcap + sigmoid
    gates_kernel<<<Mc / 8, 256>>>(Wi, Wf, Wo);

    // 4) mLSTM recurrence; also writes H_final into out[OUT_Y..]
    recurrence_kernel<<<Bc * NHc, 256>>>(out + OUT_Y);

    // 5) output projection + residual -> out[0..OUT_Y)
    sgemm_kernel<true><<<ggrid, 256>>>(p_h, Wout, x, out, Mc, Dc, Dc);
}

// round 4
// speedup vs baseline: 2.0863x; 2.0863x over previous
#include <cuda_runtime.h>
#include <math.h>
#include <stdint.h>

// Problem constants
constexpr int Bc  = 8;
constexpr int Sc  = 2048;
constexpr int Dc  = 1024;
constexpr int NHc = 16;
constexpr int HDc = 64;
constexpr int Mc  = Bc * Sc;            // 16384 rows
constexpr float GATE_CAP_F = 15.0f;
constexpr float EPS_F = 1e-5f;
constexpr size_t OUT_Y = (size_t)Mc * Dc;

// ---------------- scratch ---------------------------------------------------
__device__ float g_xn[(size_t)Mc * Dc];
__device__ float g_q [(size_t)Mc * Dc];
__device__ float g_k [(size_t)Mc * Dc];
__device__ float g_v [(size_t)Mc * Dc];
__device__ float g_h [(size_t)Mc * Dc];
__device__ float g_ig[(size_t)Mc * NHc];
__device__ float g_fg[(size_t)Mc * NHc];
__device__ float g_og[(size_t)Mc * NHc];
__device__ float g_wq[(size_t)Dc * Dc];
__device__ float g_wk[(size_t)Dc * Dc];
__device__ float g_wv[(size_t)Dc * Dc];
__device__ float g_wo[(size_t)Dc * Dc];

// ---------------- helpers ---------------------------------------------------
__device__ __forceinline__ float to_tf32(float x) {
    uint32_t y;                                   // cvt.*.tf32 dst must be .b32
    asm("cvt.rna.tf32.f32 %0, %1;" : "=r"(y) : "f"(x));
    return __uint_as_float(y);
}
__device__ __forceinline__ uint32_t smem_u32(const void* p) {
    uint32_t a;
    asm("{ .reg .u64 t; cvta.to.shared.u64 t, %1; cvt.u32.u64 %0, t; }" : "=r"(a) : "l"(p));
    return a;
}
#define CP_ASYNC16(dst, src) \
    asm volatile("cp.async.cg.shared.global [%0], [%1], 16;" :: "r"(dst), "l"(src) : "memory")
#define CP_COMMIT() asm volatile("cp.async.commit_group;" ::: "memory")
#define CP_WAIT1()  asm volatile("cp.async.wait_group 1;" ::: "memory")
#define CP_WAIT0()  asm volatile("cp.async.wait_group 0;" ::: "memory")

__device__ __forceinline__ void mma_tf32(float* d, const uint32_t* a, const uint32_t* b) {
    asm volatile(
        "mma.sync.aligned.m16n8k8.row.col.f32.tf32.tf32.f32 "
        "{%0,%1,%2,%3}, {%4,%5,%6,%7}, {%8,%9}, {%0,%1,%2,%3};"
        : "+f"(d[0]), "+f"(d[1]), "+f"(d[2]), "+f"(d[3])
        : "r"(a[0]), "r"(a[1]), "r"(a[2]), "r"(a[3]), "r"(b[0]), "r"(b[1]));
}

// ---------------- tf32 mma.sync GEMM ----------------------------------------
// C[M,N] = A[M,K] * Bw[N,K]^T (+res). BM=BN=128, BK=16, 256 thr, warp 64x32.
constexpr int GBM = 128, GBN = 128, GBK = 16;
constexpr int LDT = GBK + 4;                 // 20-float stride: conflict-free

template<bool ADD_RES>
__global__ __launch_bounds__(256, 2) void tf32_gemm_kernel(
    const float* __restrict__ A, const float* __restrict__ Bw,
    const float* __restrict__ res, float* __restrict__ C,
    int M, int N, int K)
{
    __shared__ float As[2][GBM][LDT];
    __shared__ float Bs[2][GBM][LDT];

    const int tid  = threadIdx.x;
    const int wid  = tid >> 5;
    const int lane = tid & 31;
    const int wm   = wid >> 2;          // 0..1  -> 64 rows
    const int wn   = wid & 3;           // 0..3  -> 32 cols
    const int gid  = lane >> 2;         // 0..7
    const int tg   = lane & 3;          // 0..3
    const int brow = blockIdx.y * GBM;
    const int bcol = blockIdx.x * GBN;

    const uint32_t sA0 = smem_u32(&As[0][0][0]);
    const uint32_t sB0 = smem_u32(&Bs[0][0][0]);
    constexpr uint32_t BUFB = GBM * LDT * 4;  // bytes per buffer

    const int r0 = tid >> 2;            // 0..63 row within first half
    const int sg = tid & 3;             // 16B segment

    float acc[4][4][4];
    #pragma unroll
    for (int i = 0; i < 4; i++)
        #pragma unroll
        for (int j = 0; j < 4; j++)
            #pragma unroll
            for (int c = 0; c < 4; c++) acc[i][j][c] = 0.f;

    const int KCH = K / GBK;            // 64

    auto load_tile = [&](int buf, int ch) {
        const int k0 = ch * GBK;
        #pragma unroll
        for (int i = 0; i < 2; i++) {
            const int row = r0 + i * 64;
            const uint32_t off = buf * BUFB + (row * LDT + sg * 4) * 4;
            CP_ASYNC16(sA0 + off, A  + (size_t)(brow + row) * K + k0 + sg * 4);
            CP_ASYNC16(sB0 + off, Bw + (size_t)(bcol + row) * K + k0 + sg * 4);
        }
        CP_COMMIT();
    };

    load_tile(0, 0);

    for (int ch = 0; ch < KCH; ch++) {
        const int buf = ch & 1;
        if (ch + 1 < KCH) load_tile(buf ^ 1, ch + 1);
        if (ch + 1 < KCH) CP_WAIT1(); else CP_WAIT0();
        __syncthreads();

        #pragma unroll
        for (int ks = 0; ks < 2; ks++) {
            const int k = ks * 8 + tg;
            uint32_t af[4][4], bf[4][2];
            #pragma unroll
            for (int mt = 0; mt < 4; mt++) {
                const int r = wm * 64 + mt * 16 + gid;
                af[mt][0] = __float_as_uint(As[buf][r    ][k]);
                af[mt][1] = __float_as_uint(As[buf][r + 8][k]);
                af[mt][2] = __float_as_uint(As[buf][r    ][k + 4]);
                af[mt][3] = __float_as_uint(As[buf][r + 8][k + 4]);
            }
            #pragma unroll
            for (int nt = 0; nt < 4; nt++) {
                const int n = wn * 32 + nt * 8 + gid;
                bf[nt][0] = __float_as_uint(Bs[buf][n][k]);
                bf[nt][1] = __float_as_uint(Bs[buf][n][k + 4]);
            }
            #pragma unroll
            for (int mt = 0; mt < 4; mt++)
                #pragma unroll
                for (int nt = 0; nt < 4; nt++)
                    mma_tf32(acc[mt][nt], af[mt], bf[nt]);
        }
        __syncthreads();
    }

    // epilogue: c0,c1 -> (row, col..col+1); c2,c3 -> (row+8, col..col+1)
    #pragma unroll
    for (int mt = 0; mt < 4; mt++) {
        const int row = brow + wm * 64 + mt * 16 + gid;
        #pragma unroll
        for (int nt = 0; nt < 4; nt++) {
            const int col = bcol + wn * 32 + nt * 8 + tg * 2;
            size_t p0 = (size_t)row * N + col;
            size_t p1 = (size_t)(row + 8) * N + col;
            float2 v0 = make_float2(acc[mt][nt][0], acc[mt][nt][1]);
            float2 v1 = make_float2(acc[mt][nt][2], acc[mt][nt][3]);
            if (ADD_RES) {
                float2 r0v = *(const float2*)(res + p0);
                float2 r1v = *(const float2*)(res + p1);
                v0.x += r0v.x; v0.y += r0v.y;
                v1.x += r1v.x; v1.y += r1v.y;
            }
            *(float2*)(C + p0) = v0;
            *(float2*)(C + p1) = v1;
        }
    }
}

// ---------------- RMSNorm (writes tf32-rounded xn) --------------------------
__global__ __launch_bounds__(256) void rmsnorm_kernel(const float* __restrict__ x,
                                                      const float* __restrict__ w)
{
    int row = blockIdx.x;
    const float4* xr = (const float4*)(x + (size_t)row * Dc);
    float4 v = xr[threadIdx.x];
    float ss = v.x * v.x + v.y * v.y + v.z * v.z + v.w * v.w;
    #pragma unroll
    for (int o = 16; o; o >>= 1) ss += __shfl_xor_sync(~0u, ss, o);
    __shared__ float sred[8];
    __shared__ float s_scale;
    if ((threadIdx.x & 31) == 0) sred[threadIdx.x >> 5] = ss;
    __syncthreads();
    if (threadIdx.x == 0) {
        float tot = 0.f;
        #pragma unroll
        for (int i = 0; i < 8; i++) tot += sred[i];
        s_scale = 1.0f / sqrtf(tot * (1.0f / (float)Dc) + EPS_F);
    }
    __syncthreads();
    float sc = s_scale;
    float4 ww = ((const float4*)w)[threadIdx.x];
    float4 o4;
    o4.x = to_tf32(v.x * sc * ww.x);
    o4.y = to_tf32(v.y * sc * ww.y);
    o4.z = to_tf32(v.z * sc * ww.z);
    o4.w = to_tf32(v.w * sc * ww.w);
    ((float4*)(g_xn + (size_t)row * Dc))[threadIdx.x] = o4;
}

// ---------------- weight rounding -------------------------------------------
__global__ __launch_bounds__(256) void round_w_kernel(const float* __restrict__ in,
                                                      float* __restrict__ out)
{
    int i = blockIdx.x * 256 + threadIdx.x;
    float4 v = ((const float4*)in)[i];
    v.x = to_tf32(v.x); v.y = to_tf32(v.y); v.z = to_tf32(v.z); v.w = to_tf32(v.w);
    ((float4*)out)[i] = v;
}

// ---------------- gates -----------------------------------------------------
__global__ __launch_bounds__(256) void gates_kernel(const float* __restrict__ Wi,
                                                    const float* __restrict__ Wf,
                                                    const float* __restrict__ Wo)
{
    __shared__ float sx[8][Dc];
    int row0 = blockIdx.x * 8;
    for (int idx = threadIdx.x; idx < 8 * Dc; idx += 256)
        sx[idx >> 10][idx & 1023] = g_xn[(size_t)(row0 + (idx >> 10)) * Dc + (idx & 1023)];
    __syncthreads();
    int w = threadIdx.x >> 5, lane = threadIdx.x & 31;
    int row = row0 + w;
    const float* xr = sx[w];
    for (int c = 0; c < 48; c++) {
        const float* wp = (c < 16) ? (Wi + (size_t)c * Dc)
                        : (c < 32) ? (Wf + (size_t)(c - 16) * Dc)
                                   : (Wo + (size_t)(c - 32) * Dc);
        float s = 0.f;
        #pragma unroll 8
        for (int k = lane; k < Dc; k += 32)
            s = fmaf(xr[k], __ldg(wp + k), s);
        #pragma unroll
        for (int o = 16; o; o >>= 1) s += __shfl_xor_sync(~0u, s, o);
        if (lane == 0) {
            float z  = GATE_CAP_F * tanhf(s * (1.0f / GATE_CAP_F));
            float gv = 1.0f / (1.0f + expf(-z));
            float* dst = (c < 16) ? g_ig : (c < 32) ? g_fg : g_og;
            dst[(size_t)row * NHc + (c & 15)] = gv;
        }
    }
}

// ---------------- recurrence ------------------------------------------------
__global__ __launch_bounds__(256) void recurrence_kernel(float* __restrict__ Hfinal_out)
{
    constexpr int CH = 16;
    int bh = blockIdx.x;
    int b = bh >> 4, h = bh & 15;
    int tid = threadIdx.x;
    int e = tid >> 2;
    int dg = tid & 3;
    int dbase = dg * 16;

    __shared__ float sq[CH][64], sk[CH][64], sv[CH][64], sh[CH][64];
    __shared__ float sgi[CH], sgf[CH], sgo[CH];
    float4 H4[4] = {};
    size_t baseq = (size_t)b * Sc * Dc + (size_t)h * HDc;
    size_t baseg = (size_t)b * Sc * NHc + h;

    for (int t0 = 0; t0 < Sc; t0 += CH) {
        for (int idx = tid; idx < CH * 64; idx += 256) {
            int t = idx >> 6, d = idx & 63;
            size_t g = baseq + (size_t)(t0 + t) * Dc + d;
            sq[t][d] = g_q[g]; sk[t][d] = g_k[g]; sv[t][d] = g_v[g];
        }
        if (tid < CH) {
            size_t gg = baseg + (size_t)(t0 + tid) * NHc;
            sgi[tid] = g_ig[gg]; sgf[tid] = g_fg[gg]; sgo[tid] = g_og[gg];
        }
        __syncthreads();
        #pragma unroll 4
        for (int t = 0; t < CH; t++) {
            float f = sgf[t];
            float iv = sgi[t] * sv[t][e];
            const float4* q4 = (const float4*)(&sq[t][dbase]);
            const float4* k4 = (const float4*)(&sk[t][dbase]);
            float acc = 0.f;
            #pragma unroll
            for (int j = 0; j < 4; j++) {
                float4 kk = k4[j], qq = q4[j];
                H4[j].x = fmaf(f, H4[j].x, kk.x * iv); acc = fmaf(qq.x, H4[j].x, acc);
                H4[j].y = fmaf(f, H4[j].y, kk.y * iv); acc = fmaf(qq.y, H4[j].y, acc);
                H4[j].z = fmaf(f, H4[j].z, kk.z * iv); acc = fmaf(qq.z, H4[j].z, acc);
                H4[j].w = fmaf(f, H4[j].w, kk.w * iv); acc = fmaf(qq.w, H4[j].w, acc);
            }
            acc += __shfl_xor_sync(~0u, acc, 1);
            acc += __shfl_xor_sync(~0u, acc, 2);
            if (dg == 0) sh[t][e] = to_tf32(acc * sgo[t]);
        }
        __syncthreads();
        for (int idx = tid; idx < CH * 64; idx += 256) {
            int t = idx >> 6, d = idx & 63;
            g_h[baseq + (size_t)(t0 + t) * Dc + d] = sh[t][d];
        }
    }
    float* Hf = Hfinal_out + (size_t)bh * 64 * 64;
    #pragma unroll
    for (int j = 0; j < 4; j++) {
        int d = dbase + j * 4;
        Hf[(size_t)(d + 0) * 64 + e] = H4[j].x;
        Hf[(size_t)(d + 1) * 64 + e] = H4[j].y;
        Hf[(size_t)(d + 2) * 64 + e] = H4[j].z;
        Hf[(size_t)(d + 3) * 64 + e] = H4[j].w;
    }
}

// ---------------- launch ----------------------------------------------------
extern "C" void kernel_launch(void* const* d_in, const int* in_sizes, int n_in,
                              void* d_out, int out_size)
{
    const float* x    = (const float*)d_in[0];
    const float* Wq   = (const float*)d_in[1];
    const float* Wk   = (const float*)d_in[2];
    const float* Wv   = (const float*)d_in[3];
    const float* Wi   = (const float*)d_in[4];
    const float* Wf   = (const float*)d_in[5];
    const float* Wo   = (const float*)d_in[6];
    const float* Wout = (const float*)d_in[7];
    const float* lnw  = (const float*)d_in[8];
    float* out = (float*)d_out;

    float *p_xn, *p_q, *p_k, *p_v, *p_h, *p_wq, *p_wk, *p_wv, *p_wo;
    cudaGetSymbolAddress((void**)&p_xn, g_xn);
    cudaGetSymbolAddress((void**)&p_q,  g_q);
    cudaGetSymbolAddress((void**)&p_k,  g_k);
    cudaGetSymbolAddress((void**)&p_v,  g_v);
    cudaGetSymbolAddress((void**)&p_h,  g_h);
    cudaGetSymbolAddress((void**)&p_wq, g_wq);
    cudaGetSymbolAddress((void**)&p_wk, g_wk);
    cudaGetSymbolAddress((void**)&p_wv, g_wv);
    cudaGetSymbolAddress((void**)&p_wo, g_wo);

    // 1) RMSNorm -> tf32-rounded xn
    rmsnorm_kernel<<<Mc, 256>>>(x, lnw);

    // 2) round weights to tf32 (exact in-MMA truncation)
    int wblocks = (Dc * Dc / 4) / 256;
    round_w_kernel<<<wblocks, 256>>>(Wq,   p_wq);
    round_w_kernel<<<wblocks, 256>>>(Wk,   p_wk);
    round_w_kernel<<<wblocks, 256>>>(Wv,   p_wv);
    round_w_kernel<<<wblocks, 256>>>(Wout, p_wo);

    // 3) Q/K/V projections via mma.sync tf32
    dim3 ggrid(Dc / GBN, Mc / GBM);        // (8, 128)
    tf32_gemm_kernel<false><<<ggrid, 256>>>(p_xn, p_wq, nullptr, p_q, Mc, Dc, Dc);
    tf32_gemm_kernel<false><<<ggrid, 256>>>(p_xn, p_wk, nullptr, p_k, Mc, Dc, Dc);
    tf32_gemm_kernel<false><<<ggrid, 256>>>(p_xn, p_wv, nullptr, p_v, Mc, Dc, Dc);

    // 4) gates
    gates_kernel<<<Mc / 8, 256>>>(Wi, Wf, Wo);

    // 5) recurrence (+ H_final)
    recurrence_kernel<<<Bc * NHc, 256>>>(out + OUT_Y);

    // 6) output projection + residual
    tf32_gemm_kernel<true><<<ggrid, 256>>>(p_h, p_wo, x, out, Mc, Dc, Dc);
}